// round 2
// baseline (speedup 1.0000x reference)
#include <cuda_runtime.h>

// NormalizedCorrelation2D: out[b,t] = sum_w sum_{h,c} x1[b,h,(t+w+450)%900,c] * x2[b,h,w,c]
// B=16, H=4, W=900, C=256. fp32 SIMT band-GEMM, register tile 12x8.

#define B_ 16
#define H_ 4
#define W_ 900
#define C_ 256
#define D_ 1024
#define NPAD 450

#define TT 96                    // t-tile per block
#define SW 128                   // w per smem step
#define SD 32                    // d per smem step
#define BAND (TT + SW)           // 224 band rows
#define X1_STRIDE (BAND + 4)     // 228 (mult of 4 for LDS.128 alignment)
#define X2_STRIDE (SW + 4)       // 132
#define RT 12                    // t per thread
#define RW 8                     // w per thread
#define NTHREADS 128             // 8 t-groups x 16 w-groups
#define NTILES_T 10              // ceil(900/96)
#define WSPLIT 4
#define NSTEPS_W 8               // w in [0,1024) padded, 8 steps of 128

// partial sums: [B][WSPLIT][W]  (each slot written by exactly one block -> deterministic)
__device__ float g_psum[B_ * WSPLIT * W_];

__global__ __launch_bounds__(NTHREADS)
void corr_kernel(const float* __restrict__ x1, const float* __restrict__ x2) {
    __shared__ float X1T[SD * X1_STRIDE];   // d-major transposed band: X1T[d][r]
    __shared__ float X2T[SD * X2_STRIDE];   // X2T[d][j]

    const int bx    = blockIdx.x;
    const int ws    = bx & (WSPLIT - 1);
    const int tileT = (bx >> 2) % NTILES_T;
    const int b     = bx / (WSPLIT * NTILES_T);
    const int t0    = tileT * TT;

    const int tid = threadIdx.x;
    const int tg  = tid & 7;      // t-group 0..7
    const int wg  = tid >> 3;     // w-group 0..15
    const int ib  = tg * RT + wg * RW;  // band-frag base (mult of 4)
    const int jb  = wg * RW;            // x2-frag base  (mult of 4)

    float acc[RT];
#pragma unroll
    for (int i = 0; i < RT; i++) acc[i] = 0.f;

    const float* x1b = x1 + (size_t)b * H_ * W_ * C_;
    const float* x2b = x2 + (size_t)b * H_ * W_ * C_;

    for (int sidx = ws; sidx < NSTEPS_W; sidx += WSPLIT) {
        const int wb = sidx * SW;
        int s0 = (t0 + wb + NPAD) % W_;   // band start row in x1

        for (int db = 0; db < D_; db += SD) {
            const int h     = db >> 8;
            const int cbase = db & 255;
            __syncthreads();   // previous compute done before overwrite

            // ---- load x1 band: BAND rows x SD cols, transposed into smem ----
            {
                const float* src = x1b + (size_t)h * W_ * C_ + cbase;
#pragma unroll
                for (int it = 0; it < (BAND * (SD / 4)) / NTHREADS; it++) {
                    int idx = it * NTHREADS + tid;
                    int r = idx >> 3;          // band row
                    int v = idx & 7;           // float4 index along d
                    int row = s0 + r; if (row >= W_) row -= W_;
                    float4 val = *reinterpret_cast<const float4*>(src + row * C_ + v * 4);
                    int base = (v * 4) * X1_STRIDE + r;
                    X1T[base]                 = val.x;
                    X1T[base +     X1_STRIDE] = val.y;
                    X1T[base + 2 * X1_STRIDE] = val.z;
                    X1T[base + 3 * X1_STRIDE] = val.w;
                }
            }
            // ---- load x2 tile: SW rows x SD cols, transposed; zero-pad w>=900 ----
            {
                const float* src = x2b + (size_t)h * W_ * C_ + cbase;
#pragma unroll
                for (int it = 0; it < (SW * (SD / 4)) / NTHREADS; it++) {
                    int idx = it * NTHREADS + tid;
                    int r = idx >> 3;
                    int v = idx & 7;
                    int w = wb + r;
                    float4 val = (w < W_)
                        ? *reinterpret_cast<const float4*>(src + w * C_ + v * 4)
                        : make_float4(0.f, 0.f, 0.f, 0.f);
                    int base = (v * 4) * X2_STRIDE + r;
                    X2T[base]                 = val.x;
                    X2T[base +     X2_STRIDE] = val.y;
                    X2T[base + 2 * X2_STRIDE] = val.z;
                    X2T[base + 3 * X2_STRIDE] = val.w;
                }
            }
            __syncthreads();

            // ---- compute: 96 FMA per 7 LDS.128 per thread per d ----
#pragma unroll 2
            for (int dd = 0; dd < SD; dd++) {
                float x1f[RT + RW];   // 20 (covers i = ib .. ib+18)
                float x2f[RW];
                const float4* p1 = reinterpret_cast<const float4*>(&X1T[dd * X1_STRIDE + ib]);
                const float4* p2 = reinterpret_cast<const float4*>(&X2T[dd * X2_STRIDE + jb]);
#pragma unroll
                for (int q = 0; q < 5; q++) {
                    float4 v = p1[q];
                    x1f[4*q] = v.x; x1f[4*q+1] = v.y; x1f[4*q+2] = v.z; x1f[4*q+3] = v.w;
                }
#pragma unroll
                for (int q = 0; q < 2; q++) {
                    float4 v = p2[q];
                    x2f[4*q] = v.x; x2f[4*q+1] = v.y; x2f[4*q+2] = v.z; x2f[4*q+3] = v.w;
                }
#pragma unroll
                for (int tt = 0; tt < RT; tt++) {
#pragma unroll
                    for (int ww = 0; ww < RW; ww++) {
                        acc[tt] += x1f[tt + ww] * x2f[ww];
                    }
                }
            }
        }
    }

    // ---- reduce over the 16 w-groups within the block ----
    __syncthreads();
    float* red = X1T;   // reuse smem: TT*16 = 1536 floats
#pragma unroll
    for (int tt = 0; tt < RT; tt++)
        red[(tg * RT + tt) * 16 + wg] = acc[tt];
    __syncthreads();

    if (tid < TT) {
        int tglob = t0 + tid;
        if (tglob < W_) {
            float s = 0.f;
#pragma unroll
            for (int k = 0; k < 16; k++) s += red[tid * 16 + k];
            g_psum[(b * WSPLIT + ws) * W_ + tglob] = s;
        }
    }
}

__global__ void reduce_kernel(float* __restrict__ out) {
    int idx = blockIdx.x * blockDim.x + threadIdx.x;
    if (idx < B_ * W_) {
        int b = idx / W_;
        int t = idx - b * W_;
        float s = 0.f;
#pragma unroll
        for (int k = 0; k < WSPLIT; k++)
            s += g_psum[(b * WSPLIT + k) * W_ + t];
        out[idx] = s;
    }
}

extern "C" void kernel_launch(void* const* d_in, const int* in_sizes, int n_in,
                              void* d_out, int out_size) {
    const float* x1 = (const float*)d_in[0];
    const float* x2 = (const float*)d_in[1];
    float* out = (float*)d_out;

    corr_kernel<<<B_ * NTILES_T * WSPLIT, NTHREADS>>>(x1, x2);
    reduce_kernel<<<(B_ * W_ + 255) / 256, 256>>>(out);
}

// round 6
// speedup vs baseline: 2.1420x; 2.1420x over previous
#include <cuda_runtime.h>
#include <cstdint>

// out[b,t] = sum_w <x1[b,:,(t+w+450)%900,:], x2[b,:,w,:]>
//          = sum over Gram G[b,i,j] = <a1_i, a2_j> along circular diagonals.
// mma.sync tf32 (sm_80 ISA -- harness PTX target is compute_103 without 'a',
// so tcgen05 is unavailable). 16 batched 900x900x1024 GEMMs, 128x128 tiles.

#define W_ 900
#define B_ 16
#define NT 8          // 8 tiles of 128 covering 1024 >= 900
#define TM 128
#define KC 32         // K floats per stage
#define NK 32         // 1024 / 32
#define NTHREADS 256

__device__ float g_part[B_ * NT * NT * 256];

// ---------------- PTX helpers (all plain sm_80-level) ----------------
__device__ __forceinline__ uint32_t smem_u32(const void* p) {
    uint32_t a;
    asm("{ .reg .u64 t; cvta.to.shared.u64 t, %1; cvt.u32.u64 %0, t; }" : "=r"(a) : "l"(p));
    return a;
}
__device__ __forceinline__ void cp16(uint32_t dst, const void* src, int sz) {
    asm volatile("cp.async.cg.shared.global [%0], [%1], 16, %2;"
                 :: "r"(dst), "l"(src), "r"(sz) : "memory");
}
__device__ __forceinline__ void cp_commit() {
    asm volatile("cp.async.commit_group;" ::: "memory");
}
__device__ __forceinline__ void cp_wait2() {
    asm volatile("cp.async.wait_group 2;" ::: "memory");
}
__device__ __forceinline__ void ldm4(uint32_t* r, uint32_t a) {
    asm volatile("ldmatrix.sync.aligned.m8n8.x4.shared.b16 {%0,%1,%2,%3}, [%4];"
                 : "=r"(r[0]), "=r"(r[1]), "=r"(r[2]), "=r"(r[3]) : "r"(a));
}
__device__ __forceinline__ uint32_t tf32r(uint32_t x) {
    uint32_t o; float f = __uint_as_float(x);
    asm("cvt.rna.tf32.f32 %0, %1;" : "=r"(o) : "f"(f));
    return o;
}
__device__ __forceinline__ void mma_t(float* c, const uint32_t* a, uint32_t b0, uint32_t b1) {
    asm volatile("mma.sync.aligned.m16n8k8.row.col.f32.tf32.tf32.f32 "
                 "{%0,%1,%2,%3}, {%4,%5,%6,%7}, {%8,%9}, {%0,%1,%2,%3};"
                 : "+f"(c[0]), "+f"(c[1]), "+f"(c[2]), "+f"(c[3])
                 : "r"(a[0]), "r"(a[1]), "r"(a[2]), "r"(a[3]), "r"(b0), "r"(b1));
}

// Issue one K-stage of cp.async loads (A tile + B tile, zfill past row 899).
__device__ __forceinline__ void issue_stage(
    int s, const float* __restrict__ x1, const float* __restrict__ x2,
    int b, int i0, int j0, uint32_t sbase, int crow, int cchk)
{
    const int buf = s & 3;
    const int h  = (s * KC) >> 8;
    const int cb = (s * KC) & 255;
    const float* baseA = x1 + (size_t)(b * 4 + h) * W_ * 256 + cb + cchk * 4;
    const float* baseB = x2 + (size_t)(b * 4 + h) * W_ * 256 + cb + cchk * 4;
    const uint32_t dA0 = sbase + (uint32_t)buf * 32768u;
#pragma unroll
    for (int q = 0; q < 4; ++q) {
        int row = q * 32 + crow;
        uint32_t doff = (uint32_t)row * 128u + (uint32_t)((cchk ^ (row & 7)) << 4);
        int ga = i0 + row;
        int gb = j0 + row;
        int szA = (ga < W_) ? 16 : 0; if (ga >= W_) ga = 0;
        int szB = (gb < W_) ? 16 : 0; if (gb >= W_) gb = 0;
        cp16(dA0 + doff,          baseA + (size_t)ga * 256, szA);
        cp16(dA0 + 16384u + doff, baseB + (size_t)gb * 256, szB);
    }
    cp_commit();
}

// ---------------- main GEMM kernel ----------------
__global__ __launch_bounds__(NTHREADS, 1)
void corr_mma(const float* __restrict__ x1, const float* __restrict__ x2) {
    extern __shared__ float smem[];
    const uint32_t sbase = smem_u32(smem);

    const int tid  = threadIdx.x;
    const int lane = tid & 31;
    const int wid  = tid >> 5;
    const int warp_m = wid & 3;    // 4 warps along i (32 rows each)
    const int warp_n = wid >> 2;   // 2 warps along j (64 cols each)

    const int bx = blockIdx.x;
    const int tj = bx & 7;
    const int ti = (bx >> 3) & 7;
    const int b  = bx >> 6;
    const int i0 = ti * TM;
    const int j0 = tj * TM;

    float acc[2][8][4];
#pragma unroll
    for (int m = 0; m < 2; ++m)
#pragma unroll
        for (int n = 0; n < 8; ++n)
#pragma unroll
            for (int k = 0; k < 4; ++k) acc[m][n][k] = 0.f;

    // cp.async per-thread mapping: 16B chunk cchk of row crow (+32 per q)
    const int crow = tid >> 3;
    const int cchk = tid & 7;

    // ldmatrix per-thread row bases: thread supplies row (lane&7) of matrix (lane>>3)
    const int qm = lane >> 3;
    const int lr = lane & 7;
    const int qh = qm >> 1;        // k-half select (chunk offset)
    const int ql = qm & 1;         // +8 rows select
    const int rA = warp_m * 32 + ql * 8 + lr;   // + mt*16
    const int rB = warp_n * 64 + ql * 8 + lr;   // + np*16

    issue_stage(0, x1, x2, b, i0, j0, sbase, crow, cchk);
    issue_stage(1, x1, x2, b, i0, j0, sbase, crow, cchk);
    issue_stage(2, x1, x2, b, i0, j0, sbase, crow, cchk);

    for (int s = 0; s < NK; ++s) {
        cp_wait2();
        __syncthreads();   // stage s data visible to all; all warps done with buf (s-1)&3
        if (s + 3 < NK) issue_stage(s + 3, x1, x2, b, i0, j0, sbase, crow, cchk);
        else            cp_commit();   // empty group keeps wait_group 2 semantics exact

        const uint32_t Ab = sbase + (uint32_t)(s & 3) * 32768u;
        const uint32_t Bb = Ab + 16384u;

#pragma unroll
        for (int kk = 0; kk < 4; ++kk) {
            uint32_t a[2][4], bf[4][4];
#pragma unroll
            for (int mt = 0; mt < 2; ++mt) {
                int row = rA + mt * 16;
                ldm4(a[mt], Ab + (uint32_t)row * 128u
                               + (uint32_t)(((2 * kk + qh) ^ (row & 7)) << 4));
            }
#pragma unroll
            for (int np = 0; np < 4; ++np) {
                int row = rB + np * 16;
                ldm4(bf[np], Bb + (uint32_t)row * 128u
                                + (uint32_t)(((2 * kk + qh) ^ (row & 7)) << 4));
            }
            // round-to-nearest fp32 -> tf32 (kills truncation bias)
#pragma unroll
            for (int mt = 0; mt < 2; ++mt)
#pragma unroll
                for (int r = 0; r < 4; ++r) a[mt][r] = tf32r(a[mt][r]);
#pragma unroll
            for (int np = 0; np < 4; ++np)
#pragma unroll
                for (int r = 0; r < 4; ++r) bf[np][r] = tf32r(bf[np][r]);

#pragma unroll
            for (int mt = 0; mt < 2; ++mt) {
#pragma unroll
                for (int nt = 0; nt < 8; ++nt) {
                    const int np = nt >> 1;
                    uint32_t b0 = (nt & 1) ? bf[np][1] : bf[np][0];
                    uint32_t b1 = (nt & 1) ? bf[np][3] : bf[np][2];
                    mma_t(acc[mt][nt], a[mt], b0, b1);
                }
            }
        }
    }

    // ---------------- epilogue: stage tile, bin diagonals ----------------
    __syncthreads();                 // all compute done before smem reuse
    float* stg = smem;               // 128 x 132 floats = 67.5KB (fits in 128KB)
#pragma unroll
    for (int mt = 0; mt < 2; ++mt) {
        const int row0 = warp_m * 32 + mt * 16 + (lane >> 2);
#pragma unroll
        for (int nt = 0; nt < 8; ++nt) {
            const int col = warp_n * 64 + nt * 8 + (lane & 3) * 2;
            stg[row0 * 132 + col]       = acc[mt][nt][0];
            stg[row0 * 132 + col + 1]   = acc[mt][nt][1];
            stg[(row0 + 8) * 132 + col]     = acc[mt][nt][2];
            stg[(row0 + 8) * 132 + col + 1] = acc[mt][nt][3];
        }
    }
    __syncthreads();

    if (tid < 255) {
        const int d = tid - 127;                    // diag i - j in [-127, 127]
        const int ilo = d > 0 ? d : 0;
        const int ihi = d < 0 ? 127 + d : 127;
        float sum = 0.f;
        for (int i = ilo; i <= ihi; ++i)
            sum += stg[i * 132 + (i - d)];
        g_part[bx * 256 + tid] = sum;
    }
}

// ---------------- final reduction: tile-diagonals -> out[b,t] ----------------
__global__ void reduce_kernel(float* __restrict__ out) {
    const int idx = blockIdx.x * blockDim.x + threadIdx.x;
    if (idx >= B_ * W_) return;
    const int b = idx / W_;
    const int t = idx - b * W_;
    float s = 0.f;
#pragma unroll
    for (int ti = 0; ti < NT; ++ti) {
#pragma unroll
        for (int tj = 0; tj < NT; ++tj) {
            int m = (t + 450 - TM * (ti - tj)) % 900;
            if (m < 0) m += 900;
            int d;
            if (m <= 127)      d = m;
            else if (m >= 773) d = m - 900;
            else               continue;
            s += g_part[((b * NT + ti) * NT + tj) * 256 + d + 127];
        }
    }
    out[idx] = s;
}

extern "C" void kernel_launch(void* const* d_in, const int* in_sizes, int n_in,
                              void* d_out, int out_size) {
    const float* x1 = (const float*)d_in[0];
    const float* x2 = (const float*)d_in[1];
    float* out = (float*)d_out;

    cudaFuncSetAttribute(corr_mma,
                         cudaFuncAttributeMaxDynamicSharedMemorySize, 131072);
    corr_mma<<<B_ * NT * NT, NTHREADS, 131072>>>(x1, x2);
    reduce_kernel<<<(B_ * W_ + 255) / 256, 256>>>(out);
}